// round 3
// baseline (speedup 1.0000x reference)
#include <cuda_runtime.h>
#include <cstdint>

#define N_FEAT 512
#define N_HID  16
#define N_CLS  40
#define MAX_NODES 100000

// Scratch (allocation-free: __device__ globals)
__device__ float g_support1[MAX_NODES * N_HID];  // X @ W1
__device__ float g_agg1[MAX_NODES * N_HID];      // segment_sum conv1
__device__ float g_h[MAX_NODES * N_HID];         // relu(agg1 + b1)
__device__ float g_agg2[MAX_NODES * N_HID];      // segment_sum of h (16-dim)

#define FMA_F32X2(d, a, b, c) \
    asm("fma.rn.f32x2 %0, %1, %2, %3;" : "=l"(d) : "l"(a), "l"(b), "l"(c))

// ---------------------------------------------------------------------------
// Kernel 0: zero both aggregation buffers
// ---------------------------------------------------------------------------
__global__ void zero_kernel(int n_float4) {
    int i = blockIdx.x * blockDim.x + threadIdx.x;
    if (i >= n_float4) return;
    float4 z = make_float4(0.f, 0.f, 0.f, 0.f);
    reinterpret_cast<float4*>(g_agg1)[i] = z;
    reinterpret_cast<float4*>(g_agg2)[i] = z;
}

// ---------------------------------------------------------------------------
// Kernel 1: support1 = X @ W1   [nNodes,512] @ [512,16]
// Warp owns 32 rows (lane = row). X staged coalesced through a transposed,
// padded smem tile; W rows read as uniform-address __ldg broadcasts.
// FMA-bound at ~128 MAC/cyc/SM via packed f32x2.
// ---------------------------------------------------------------------------
#define GK 32  // K-chunk

__global__ __launch_bounds__(256) void gemm1_kernel(
    const float* __restrict__ X, const float* __restrict__ W1, int nNodes)
{
    __shared__ float tile[8][GK][33];  // [warp][k][row], pad 33 -> conflict-free

    int warp = threadIdx.x >> 5;
    int lane = threadIdx.x & 31;
    int rowbase = (blockIdx.x * 8 + warp) * 32;
    int myrow = rowbase + lane;

    int c4   = lane & 7;   // float4 index within 32-float k-chunk
    int rsub = lane >> 3;  // 0..3

    unsigned long long acc[8];
    #pragma unroll
    for (int p = 0; p < 8; p++) acc[p] = 0ULL;

    for (int kc = 0; kc < N_FEAT; kc += GK) {
        // stage: 32 rows x GK floats, coalesced (4 rows x 128B per iter)
        #pragma unroll
        for (int j = 0; j < 8; j++) {
            int r = j * 4 + rsub;
            int grow = rowbase + r;
            float4 v = make_float4(0.f, 0.f, 0.f, 0.f);
            if (grow < nNodes)
                v = *reinterpret_cast<const float4*>(X + (size_t)grow * N_FEAT + kc + c4 * 4);
            tile[warp][c4 * 4 + 0][r] = v.x;
            tile[warp][c4 * 4 + 1][r] = v.y;
            tile[warp][c4 * 4 + 2][r] = v.z;
            tile[warp][c4 * 4 + 3][r] = v.w;
        }
        __syncwarp();

        #pragma unroll
        for (int k = 0; k < GK; k++) {
            float xs = tile[warp][k][lane];
            unsigned long long xx;
            asm("mov.b64 %0, {%1, %1};" : "=l"(xx) : "f"(xs));
            const ulonglong2* wr = reinterpret_cast<const ulonglong2*>(W1 + (kc + k) * N_HID);
            ulonglong2 w0 = __ldg(wr + 0);  // cols 0-3
            ulonglong2 w1 = __ldg(wr + 1);  // cols 4-7
            ulonglong2 w2 = __ldg(wr + 2);  // cols 8-11
            ulonglong2 w3 = __ldg(wr + 3);  // cols 12-15
            FMA_F32X2(acc[0], xx, w0.x, acc[0]);
            FMA_F32X2(acc[1], xx, w0.y, acc[1]);
            FMA_F32X2(acc[2], xx, w1.x, acc[2]);
            FMA_F32X2(acc[3], xx, w1.y, acc[3]);
            FMA_F32X2(acc[4], xx, w2.x, acc[4]);
            FMA_F32X2(acc[5], xx, w2.y, acc[5]);
            FMA_F32X2(acc[6], xx, w3.x, acc[6]);
            FMA_F32X2(acc[7], xx, w3.y, acc[7]);
        }
        __syncwarp();
    }

    if (myrow < nNodes) {
        float* o = g_support1 + (size_t)myrow * N_HID;
        #pragma unroll
        for (int q = 0; q < 4; q++) {
            ulonglong2 st;
            st.x = acc[q * 2 + 0];
            st.y = acc[q * 2 + 1];
            *reinterpret_cast<ulonglong2*>(o + q * 4) = st;  // coalesced 64B/lane
        }
    }
}

// ---------------------------------------------------------------------------
// Kernel 2: edge aggregation. One thread per edge: 4x LDG.128 gather,
// scale, 4x red.global.add.v4.f32.
// ---------------------------------------------------------------------------
__global__ __launch_bounds__(256) void aggregate_kernel(
    const int* __restrict__ src, const int* __restrict__ dst,
    const float* __restrict__ ew, const float* __restrict__ feat,
    float* __restrict__ out, int nEdges)
{
    int e = blockIdx.x * blockDim.x + threadIdx.x;
    if (e >= nEdges) return;

    int s = __ldg(src + e);
    int d = __ldg(dst + e);
    float w = __ldg(ew + e);

    const float4* fp = reinterpret_cast<const float4*>(feat + (size_t)s * N_HID);
    float4 v0 = fp[0], v1 = fp[1], v2 = fp[2], v3 = fp[3];

    float* o = out + (size_t)d * N_HID;
    asm volatile("red.global.add.v4.f32 [%0], {%1, %2, %3, %4};"
                 :: "l"(o), "f"(v0.x * w), "f"(v0.y * w), "f"(v0.z * w), "f"(v0.w * w) : "memory");
    asm volatile("red.global.add.v4.f32 [%0], {%1, %2, %3, %4};"
                 :: "l"(o + 4), "f"(v1.x * w), "f"(v1.y * w), "f"(v1.z * w), "f"(v1.w * w) : "memory");
    asm volatile("red.global.add.v4.f32 [%0], {%1, %2, %3, %4};"
                 :: "l"(o + 8), "f"(v2.x * w), "f"(v2.y * w), "f"(v2.z * w), "f"(v2.w * w) : "memory");
    asm volatile("red.global.add.v4.f32 [%0], {%1, %2, %3, %4};"
                 :: "l"(o + 12), "f"(v3.x * w), "f"(v3.y * w), "f"(v3.z * w), "f"(v3.w * w) : "memory");
}

// ---------------------------------------------------------------------------
// Kernel 3: h = relu(agg1 + b1)
// ---------------------------------------------------------------------------
__global__ __launch_bounds__(256) void relu_bias_kernel(
    const float* __restrict__ b1, int n_float4)
{
    int i = blockIdx.x * blockDim.x + threadIdx.x;
    if (i >= n_float4) return;
    int j = (i & 3) << 2;
    float4 v = reinterpret_cast<const float4*>(g_agg1)[i];
    float4 b = *reinterpret_cast<const float4*>(b1 + j);
    v.x = fmaxf(v.x + b.x, 0.f);
    v.y = fmaxf(v.y + b.y, 0.f);
    v.z = fmaxf(v.z + b.z, 0.f);
    v.w = fmaxf(v.w + b.w, 0.f);
    reinterpret_cast<float4*>(g_h)[i] = v;
}

// ---------------------------------------------------------------------------
// Kernel 4: out = log_softmax(agg2 @ W2 + b2)   (16-dim agg trick: project here)
// ---------------------------------------------------------------------------
__global__ __launch_bounds__(128) void head_kernel(
    const float* __restrict__ W2, const float* __restrict__ b2,
    float* __restrict__ out, int nNodes)
{
    __shared__ float sW[N_HID * N_CLS];
    __shared__ float sb[N_CLS];
    for (int i = threadIdx.x; i < N_HID * N_CLS; i += blockDim.x) sW[i] = W2[i];
    for (int i = threadIdx.x; i < N_CLS; i += blockDim.x) sb[i] = b2[i];
    __syncthreads();

    int node = blockIdx.x * blockDim.x + threadIdx.x;
    if (node >= nNodes) return;

    float v[N_HID];
    const float4* vp = reinterpret_cast<const float4*>(g_agg2 + (size_t)node * N_HID);
    #pragma unroll
    for (int q = 0; q < 4; q++) {
        float4 t = vp[q];
        v[q * 4 + 0] = t.x; v[q * 4 + 1] = t.y; v[q * 4 + 2] = t.z; v[q * 4 + 3] = t.w;
    }

    float y[N_CLS];
    #pragma unroll
    for (int c = 0; c < N_CLS; c++) y[c] = sb[c];
    #pragma unroll
    for (int k = 0; k < N_HID; k++) {
        float vk = v[k];
        const float* wr = sW + k * N_CLS;
        #pragma unroll
        for (int c = 0; c < N_CLS; c++)
            y[c] = fmaf(vk, wr[c], y[c]);
    }

    float mx = y[0];
    #pragma unroll
    for (int c = 1; c < N_CLS; c++) mx = fmaxf(mx, y[c]);
    float sum = 0.f;
    #pragma unroll
    for (int c = 0; c < N_CLS; c++) sum += __expf(y[c] - mx);
    float lse = mx + __logf(sum);

    float* o = out + (size_t)node * N_CLS;
    #pragma unroll
    for (int q = 0; q < N_CLS / 4; q++) {
        float4 st = make_float4(y[q * 4 + 0] - lse, y[q * 4 + 1] - lse,
                                y[q * 4 + 2] - lse, y[q * 4 + 3] - lse);
        *reinterpret_cast<float4*>(o + q * 4) = st;
    }
}

// ---------------------------------------------------------------------------
// Launcher
// ---------------------------------------------------------------------------
extern "C" void kernel_launch(void* const* d_in, const int* in_sizes, int n_in,
                              void* d_out, int out_size)
{
    const float* x        = (const float*)d_in[0];
    const int*   edge_src = (const int*)  d_in[1];
    const int*   edge_dst = (const int*)  d_in[2];
    const float* edge_w   = (const float*)d_in[3];
    const float* W1       = (const float*)d_in[4];
    const float* b1       = (const float*)d_in[5];
    const float* W2       = (const float*)d_in[6];
    const float* b2       = (const float*)d_in[7];
    float* out = (float*)d_out;

    int nNodes = in_sizes[0] / N_FEAT;
    int nEdges = in_sizes[1];

    float* d_support1; cudaGetSymbolAddress((void**)&d_support1, g_support1);
    float* d_agg1;     cudaGetSymbolAddress((void**)&d_agg1, g_agg1);
    float* d_h;        cudaGetSymbolAddress((void**)&d_h, g_h);
    float* d_agg2;     cudaGetSymbolAddress((void**)&d_agg2, g_agg2);

    int n_f4 = nNodes * N_HID / 4;

    zero_kernel<<<(n_f4 + 255) / 256, 256>>>(n_f4);

    int rows_per_block = 256;  // 8 warps x 32 rows
    gemm1_kernel<<<(nNodes + rows_per_block - 1) / rows_per_block, 256>>>(x, W1, nNodes);

    aggregate_kernel<<<(nEdges + 255) / 256, 256>>>(
        edge_src, edge_dst, edge_w, d_support1, d_agg1, nEdges);

    relu_bias_kernel<<<(n_f4 + 255) / 256, 256>>>(b1, n_f4);

    aggregate_kernel<<<(nEdges + 255) / 256, 256>>>(
        edge_src, edge_dst, edge_w, d_h, d_agg2, nEdges);

    head_kernel<<<(nNodes + 127) / 128, 128>>>(W2, b2, out, nNodes);
}

// round 4
// speedup vs baseline: 1.1426x; 1.1426x over previous
#include <cuda_runtime.h>
#include <cstdint>

#define N_FEAT 512
#define N_HID  16
#define N_CLS  40
#define MAX_NODES 100000

// Scratch (allocation-free: __device__ globals)
__device__ float g_support1[MAX_NODES * N_HID];  // X @ W1
__device__ float g_agg1[MAX_NODES * N_HID];      // segment_sum conv1
__device__ float g_h[MAX_NODES * N_HID];         // relu(agg1 + b1)
__device__ float g_agg2[MAX_NODES * N_HID];      // segment_sum of h (16-dim)

#define FMA_F32X2(d, a, b, c) \
    asm("fma.rn.f32x2 %0, %1, %2, %3;" : "=l"(d) : "l"(a), "l"(b), "l"(c))

// ---------------------------------------------------------------------------
// Kernel 0: zero both aggregation buffers
// ---------------------------------------------------------------------------
__global__ void zero_kernel(int n_float4) {
    int i = blockIdx.x * blockDim.x + threadIdx.x;
    if (i >= n_float4) return;
    float4 z = make_float4(0.f, 0.f, 0.f, 0.f);
    reinterpret_cast<float4*>(g_agg1)[i] = z;
    reinterpret_cast<float4*>(g_agg2)[i] = z;
}

// ---------------------------------------------------------------------------
// Kernel 1: support1 = X @ W1   [nNodes,512] @ [512,16]
// 256 threads/block, 2 rows/thread (t and t+256) => 512 rows/block.
// X staged coalesced through padded smem tile[512][17] in K-chunks of 16.
// W rows via uniform __ldg broadcasts, amortized over 2 rows.
// ---------------------------------------------------------------------------
#define GKC 16          // K-chunk
#define GROWS 512       // rows per block
#define GPAD 17         // tile row stride (odd -> conflict-free reads)

__global__ __launch_bounds__(256) void gemm1_kernel(
    const float* __restrict__ X, const float* __restrict__ W1, int nNodes)
{
    __shared__ float tile[GROWS * GPAD];  // 34.8 KB

    int t = threadIdx.x;
    int rowbase = blockIdx.x * GROWS;
    int r0 = rowbase + t;          // row A
    int r1 = rowbase + t + 256;    // row B

    unsigned long long accA[8], accB[8];
    #pragma unroll
    for (int p = 0; p < 8; p++) { accA[p] = 0ULL; accB[p] = 0ULL; }

    for (int kc = 0; kc < N_FEAT; kc += GKC) {
        // stage 512 rows x 16 floats, coalesced: 2048 float4, 8 per thread
        #pragma unroll
        for (int j = 0; j < 8; j++) {
            int idx = t + 256 * j;
            int row = idx >> 2;        // 0..511
            int c4  = idx & 3;         // 0..3
            int grow = rowbase + row;
            float4 v = make_float4(0.f, 0.f, 0.f, 0.f);
            if (grow < nNodes)
                v = *reinterpret_cast<const float4*>(
                        X + (size_t)grow * N_FEAT + kc + c4 * 4);
            float* tp = tile + row * GPAD + c4 * 4;
            tp[0] = v.x; tp[1] = v.y; tp[2] = v.z; tp[3] = v.w;
        }
        __syncthreads();

        const float* tA = tile + t * GPAD;
        const float* tB = tile + (t + 256) * GPAD;

        #pragma unroll
        for (int kk = 0; kk < GKC; kk++) {
            float xa = tA[kk];
            float xb = tB[kk];
            unsigned long long xxa, xxb;
            asm("mov.b64 %0, {%1, %1};" : "=l"(xxa) : "f"(xa));
            asm("mov.b64 %0, {%1, %1};" : "=l"(xxb) : "f"(xb));

            const ulonglong2* wr =
                reinterpret_cast<const ulonglong2*>(W1 + (kc + kk) * N_HID);
            ulonglong2 w0 = __ldg(wr + 0);
            ulonglong2 w1 = __ldg(wr + 1);
            ulonglong2 w2 = __ldg(wr + 2);
            ulonglong2 w3 = __ldg(wr + 3);

            FMA_F32X2(accA[0], xxa, w0.x, accA[0]);
            FMA_F32X2(accA[1], xxa, w0.y, accA[1]);
            FMA_F32X2(accA[2], xxa, w1.x, accA[2]);
            FMA_F32X2(accA[3], xxa, w1.y, accA[3]);
            FMA_F32X2(accA[4], xxa, w2.x, accA[4]);
            FMA_F32X2(accA[5], xxa, w2.y, accA[5]);
            FMA_F32X2(accA[6], xxa, w3.x, accA[6]);
            FMA_F32X2(accA[7], xxa, w3.y, accA[7]);

            FMA_F32X2(accB[0], xxb, w0.x, accB[0]);
            FMA_F32X2(accB[1], xxb, w0.y, accB[1]);
            FMA_F32X2(accB[2], xxb, w1.x, accB[2]);
            FMA_F32X2(accB[3], xxb, w1.y, accB[3]);
            FMA_F32X2(accB[4], xxb, w2.x, accB[4]);
            FMA_F32X2(accB[5], xxb, w2.y, accB[5]);
            FMA_F32X2(accB[6], xxb, w3.x, accB[6]);
            FMA_F32X2(accB[7], xxb, w3.y, accB[7]);
        }
        __syncthreads();
    }

    if (r0 < nNodes) {
        float* o = g_support1 + (size_t)r0 * N_HID;
        #pragma unroll
        for (int q = 0; q < 4; q++) {
            ulonglong2 st; st.x = accA[q * 2]; st.y = accA[q * 2 + 1];
            *reinterpret_cast<ulonglong2*>(o + q * 4) = st;
        }
    }
    if (r1 < nNodes) {
        float* o = g_support1 + (size_t)r1 * N_HID;
        #pragma unroll
        for (int q = 0; q < 4; q++) {
            ulonglong2 st; st.x = accB[q * 2]; st.y = accB[q * 2 + 1];
            *reinterpret_cast<ulonglong2*>(o + q * 4) = st;
        }
    }
}

// ---------------------------------------------------------------------------
// Kernel 2: edge aggregation (R1 layout: 4 lanes per edge, red.global.add.v4)
// ---------------------------------------------------------------------------
__global__ __launch_bounds__(256) void aggregate_kernel(
    const int* __restrict__ src, const int* __restrict__ dst,
    const float* __restrict__ ew, const float* __restrict__ feat,
    float* __restrict__ out, int nEdges)
{
    int gid = blockIdx.x * blockDim.x + threadIdx.x;
    int e = gid >> 2;
    if (e >= nEdges) return;
    int c = (gid & 3) << 2;

    int s = __ldg(src + e);
    int d = __ldg(dst + e);
    float w = __ldg(ew + e);

    float4 v = *reinterpret_cast<const float4*>(feat + (size_t)s * N_HID + c);
    float* o = out + (size_t)d * N_HID + c;
    asm volatile("red.global.add.v4.f32 [%0], {%1, %2, %3, %4};"
                 :: "l"(o), "f"(v.x * w), "f"(v.y * w), "f"(v.z * w), "f"(v.w * w)
                 : "memory");
}

// ---------------------------------------------------------------------------
// Kernel 3: h = relu(agg1 + b1)
// ---------------------------------------------------------------------------
__global__ __launch_bounds__(256) void relu_bias_kernel(
    const float* __restrict__ b1, int n_float4)
{
    int i = blockIdx.x * blockDim.x + threadIdx.x;
    if (i >= n_float4) return;
    int j = (i & 3) << 2;
    float4 v = reinterpret_cast<const float4*>(g_agg1)[i];
    float4 b = *reinterpret_cast<const float4*>(b1 + j);
    v.x = fmaxf(v.x + b.x, 0.f);
    v.y = fmaxf(v.y + b.y, 0.f);
    v.z = fmaxf(v.z + b.z, 0.f);
    v.w = fmaxf(v.w + b.w, 0.f);
    reinterpret_cast<float4*>(g_h)[i] = v;
}

// ---------------------------------------------------------------------------
// Kernel 4: out = log_softmax(agg2 @ W2 + b2)
// ---------------------------------------------------------------------------
__global__ __launch_bounds__(128) void head_kernel(
    const float* __restrict__ W2, const float* __restrict__ b2,
    float* __restrict__ out, int nNodes)
{
    __shared__ float sW[N_HID * N_CLS];
    __shared__ float sb[N_CLS];
    for (int i = threadIdx.x; i < N_HID * N_CLS; i += blockDim.x) sW[i] = W2[i];
    for (int i = threadIdx.x; i < N_CLS; i += blockDim.x) sb[i] = b2[i];
    __syncthreads();

    int node = blockIdx.x * blockDim.x + threadIdx.x;
    if (node >= nNodes) return;

    float v[N_HID];
    const float4* vp = reinterpret_cast<const float4*>(g_agg2 + (size_t)node * N_HID);
    #pragma unroll
    for (int q = 0; q < 4; q++) {
        float4 tt = vp[q];
        v[q * 4 + 0] = tt.x; v[q * 4 + 1] = tt.y; v[q * 4 + 2] = tt.z; v[q * 4 + 3] = tt.w;
    }

    float y[N_CLS];
    #pragma unroll
    for (int c = 0; c < N_CLS; c++) y[c] = sb[c];
    #pragma unroll
    for (int k = 0; k < N_HID; k++) {
        float vk = v[k];
        const float* wr = sW + k * N_CLS;
        #pragma unroll
        for (int c = 0; c < N_CLS; c++)
            y[c] = fmaf(vk, wr[c], y[c]);
    }

    float mx = y[0];
    #pragma unroll
    for (int c = 1; c < N_CLS; c++) mx = fmaxf(mx, y[c]);
    float sum = 0.f;
    #pragma unroll
    for (int c = 0; c < N_CLS; c++) sum += __expf(y[c] - mx);
    float lse = mx + __logf(sum);

    float* o = out + (size_t)node * N_CLS;
    #pragma unroll
    for (int q = 0; q < N_CLS / 4; q++) {
        float4 st = make_float4(y[q * 4 + 0] - lse, y[q * 4 + 1] - lse,
                                y[q * 4 + 2] - lse, y[q * 4 + 3] - lse);
        *reinterpret_cast<float4*>(o + q * 4) = st;
    }
}

// ---------------------------------------------------------------------------
// Launcher
// ---------------------------------------------------------------------------
extern "C" void kernel_launch(void* const* d_in, const int* in_sizes, int n_in,
                              void* d_out, int out_size)
{
    const float* x        = (const float*)d_in[0];
    const int*   edge_src = (const int*)  d_in[1];
    const int*   edge_dst = (const int*)  d_in[2];
    const float* edge_w   = (const float*)d_in[3];
    const float* W1       = (const float*)d_in[4];
    const float* b1       = (const float*)d_in[5];
    const float* W2       = (const float*)d_in[6];
    const float* b2       = (const float*)d_in[7];
    float* out = (float*)d_out;

    int nNodes = in_sizes[0] / N_FEAT;
    int nEdges = in_sizes[1];

    float* d_support1; cudaGetSymbolAddress((void**)&d_support1, g_support1);
    float* d_agg1;     cudaGetSymbolAddress((void**)&d_agg1, g_agg1);
    float* d_h;        cudaGetSymbolAddress((void**)&d_h, g_h);
    float* d_agg2;     cudaGetSymbolAddress((void**)&d_agg2, g_agg2);

    int n_f4 = nNodes * N_HID / 4;

    zero_kernel<<<(n_f4 + 255) / 256, 256>>>(n_f4);

    gemm1_kernel<<<(nNodes + GROWS - 1) / GROWS, 256>>>(x, W1, nNodes);

    int aggThreads = nEdges * 4;
    aggregate_kernel<<<(aggThreads + 255) / 256, 256>>>(
        edge_src, edge_dst, edge_w, d_support1, d_agg1, nEdges);

    relu_bias_kernel<<<(n_f4 + 255) / 256, 256>>>(b1, n_f4);

    aggregate_kernel<<<(aggThreads + 255) / 256, 256>>>(
        edge_src, edge_dst, edge_w, d_h, d_agg2, nEdges);

    head_kernel<<<(nNodes + 127) / 128, 128>>>(W2, b2, out, nNodes);
}

// round 5
// speedup vs baseline: 1.2103x; 1.0593x over previous
#include <cuda_runtime.h>
#include <cstdint>

#define N_FEAT 512
#define N_HID  16
#define N_CLS  40
#define MAX_NODES 100000
#define MAX_EDGES 3200000
#define SCAN_B    1024
#define MAX_NB    128   // ceil(100000/1024)=98

// ---------------------------------------------------------------------------
// Scratch (allocation-free: __device__ globals)
// ---------------------------------------------------------------------------
__device__ float  g_support1[MAX_NODES * N_HID];
__device__ float  g_h[MAX_NODES * N_HID];
__device__ float2 g_ebuf[MAX_EDGES];      // dst-bucketed (src_bits, w)
__device__ int    g_deg[MAX_NODES];
__device__ int    g_rowptr[MAX_NODES];
__device__ int    g_cursor[MAX_NODES];
__device__ int    g_blksum[MAX_NB];

#define FMA_F32X2(d, a, b, c) \
    asm("fma.rn.f32x2 %0, %1, %2, %3;" : "=l"(d) : "l"(a), "l"(b), "l"(c))

// ---------------------------------------------------------------------------
// CSR build
// ---------------------------------------------------------------------------
__global__ void zero_deg_kernel(int n) {
    int i = blockIdx.x * blockDim.x + threadIdx.x;
    if (i < n) g_deg[i] = 0;
}

__global__ __launch_bounds__(256) void hist_kernel(const int* __restrict__ dst, int nEdges) {
    int e = blockIdx.x * blockDim.x + threadIdx.x;
    if (e < nEdges) atomicAdd(&g_deg[dst[e]], 1);   // no return use -> RED
}

__global__ __launch_bounds__(SCAN_B) void scanA_kernel(int n) {
    __shared__ int s[SCAN_B];
    int tid = threadIdx.x;
    int i = blockIdx.x * SCAN_B + tid;
    int v = (i < n) ? g_deg[i] : 0;
    s[tid] = v;
    __syncthreads();
    #pragma unroll
    for (int off = 1; off < SCAN_B; off <<= 1) {
        int t = (tid >= off) ? s[tid - off] : 0;
        __syncthreads();
        s[tid] += t;
        __syncthreads();
    }
    if (i < n) g_rowptr[i] = s[tid] - v;
    if (tid == SCAN_B - 1) g_blksum[blockIdx.x] = s[tid];
}

__global__ __launch_bounds__(MAX_NB) void scanB_kernel(int nb) {
    __shared__ int s[MAX_NB];
    int tid = threadIdx.x;
    int v = (tid < nb) ? g_blksum[tid] : 0;
    s[tid] = v;
    __syncthreads();
    #pragma unroll
    for (int off = 1; off < MAX_NB; off <<= 1) {
        int t = (tid >= off) ? s[tid - off] : 0;
        __syncthreads();
        s[tid] += t;
        __syncthreads();
    }
    if (tid < nb) g_blksum[tid] = s[tid] - v;
}

__global__ __launch_bounds__(256) void scanC_kernel(int n) {
    int i = blockIdx.x * blockDim.x + threadIdx.x;
    if (i >= n) return;
    int r = g_rowptr[i] + g_blksum[i >> 10];
    g_rowptr[i] = r;
    g_cursor[i] = r;
}

__global__ __launch_bounds__(256) void scatter_kernel(
    const int* __restrict__ src, const int* __restrict__ dst,
    const float* __restrict__ ew, int nEdges)
{
    int e = blockIdx.x * blockDim.x + threadIdx.x;
    if (e >= nEdges) return;
    int d = __ldg(dst + e);
    int s = __ldg(src + e);
    float w = __ldg(ew + e);
    int pos = atomicAdd(&g_cursor[d], 1);
    g_ebuf[pos] = make_float2(__int_as_float(s), w);
}

// ---------------------------------------------------------------------------
// gemm1: support1 = X @ W1  (R1's known-good version — thread per row,
// W1 in smem, X row read thread-sequentially so L1 reuses lines fully)
// ---------------------------------------------------------------------------
__global__ __launch_bounds__(256) void gemm1_kernel(
    const float* __restrict__ X, const float* __restrict__ W1, int nNodes)
{
    __shared__ __align__(16) float sW[N_FEAT * N_HID];  // 32 KB
    for (int i = threadIdx.x; i < N_FEAT * N_HID; i += blockDim.x)
        sW[i] = W1[i];
    __syncthreads();

    int row = blockIdx.x * blockDim.x + threadIdx.x;
    if (row >= nNodes) return;

    const float4* xr = reinterpret_cast<const float4*>(X + (size_t)row * N_FEAT);

    unsigned long long acc[8];
    #pragma unroll
    for (int p = 0; p < 8; p++) acc[p] = 0ULL;

    #pragma unroll 2
    for (int k4 = 0; k4 < N_FEAT / 4; k4++) {
        float4 xv = xr[k4];
        #pragma unroll
        for (int t = 0; t < 4; t++) {
            float xs = (t == 0) ? xv.x : (t == 1) ? xv.y : (t == 2) ? xv.z : xv.w;
            unsigned long long xx;
            asm("mov.b64 %0, {%1, %1};" : "=l"(xx) : "f"(xs));
            const float* wrow = sW + (k4 * 4 + t) * N_HID;
            #pragma unroll
            for (int q = 0; q < 2; q++) {
                ulonglong2 w0 = *reinterpret_cast<const ulonglong2*>(wrow + q * 8);
                FMA_F32X2(acc[q * 4 + 0], xx, w0.x, acc[q * 4 + 0]);
                FMA_F32X2(acc[q * 4 + 1], xx, w0.y, acc[q * 4 + 1]);
                ulonglong2 w1 = *reinterpret_cast<const ulonglong2*>(wrow + q * 8 + 4);
                FMA_F32X2(acc[q * 4 + 2], xx, w1.x, acc[q * 4 + 2]);
                FMA_F32X2(acc[q * 4 + 3], xx, w1.y, acc[q * 4 + 3]);
            }
        }
    }

    float* o = g_support1 + (size_t)row * N_HID;
    #pragma unroll
    for (int q = 0; q < 4; q++) {
        ulonglong2 st;
        st.x = acc[q * 2 + 0];
        st.y = acc[q * 2 + 1];
        *reinterpret_cast<ulonglong2*>(o + q * 4) = st;
    }
}

// ---------------------------------------------------------------------------
// Warp-per-node gather core: lanes in groups of 4 per edge, 8 edges/iter,
// butterfly-reduce across groups. Returns lane's float4 (valid on lanes 0-3,
// lane l holds columns 4l..4l+3).
// ---------------------------------------------------------------------------
__device__ __forceinline__ float4 warp_gather(
    int node, int lane, const float* __restrict__ feat)
{
    int beg = g_rowptr[node];
    int end = beg + g_deg[node];
    int grp = lane >> 2;          // 0..7
    int c   = (lane & 3) << 2;    // 0,4,8,12

    float4 acc = make_float4(0.f, 0.f, 0.f, 0.f);

    for (int e = beg + grp; e < end; e += 8) {
        float2 ew2 = __ldg(g_ebuf + e);          // 4 lanes same addr: merged
        int   s = __float_as_int(ew2.x);
        float w = ew2.y;
        float4 v = *reinterpret_cast<const float4*>(feat + (size_t)s * N_HID + c);
        acc.x = fmaf(v.x, w, acc.x);
        acc.y = fmaf(v.y, w, acc.y);
        acc.z = fmaf(v.z, w, acc.z);
        acc.w = fmaf(v.w, w, acc.w);
    }

    // reduce over the 8 groups (lanes sharing lane&3)
    #pragma unroll
    for (int off = 16; off >= 4; off >>= 1) {
        acc.x += __shfl_xor_sync(0xffffffffu, acc.x, off);
        acc.y += __shfl_xor_sync(0xffffffffu, acc.y, off);
        acc.z += __shfl_xor_sync(0xffffffffu, acc.z, off);
        acc.w += __shfl_xor_sync(0xffffffffu, acc.w, off);
    }
    return acc;
}

// conv1: h = relu(gather(support1) + b1)
__global__ __launch_bounds__(256) void gconv1_kernel(
    const float* __restrict__ b1, int nNodes)
{
    int lane = threadIdx.x & 31;
    int node = blockIdx.x * 8 + (threadIdx.x >> 5);
    if (node >= nNodes) return;

    float4 acc = warp_gather(node, lane, g_support1);

    if (lane < 4) {
        float4 b = *reinterpret_cast<const float4*>(b1 + lane * 4);
        acc.x = fmaxf(acc.x + b.x, 0.f);
        acc.y = fmaxf(acc.y + b.y, 0.f);
        acc.z = fmaxf(acc.z + b.z, 0.f);
        acc.w = fmaxf(acc.w + b.w, 0.f);
        *reinterpret_cast<float4*>(g_h + (size_t)node * N_HID + lane * 4) = acc;
    }
}

// conv2 + head: out = log_softmax(gather(h) @ W2 + b2)
__global__ __launch_bounds__(256) void gconv2_head_kernel(
    const float* __restrict__ W2, const float* __restrict__ b2,
    float* __restrict__ out, int nNodes)
{
    __shared__ float sW[N_HID * N_CLS];   // [k][40]
    __shared__ float sb[N_CLS];
    __shared__ float sv[8][N_HID];        // per-warp aggregated vector
    for (int i = threadIdx.x; i < N_HID * N_CLS; i += blockDim.x) sW[i] = W2[i];
    for (int i = threadIdx.x; i < N_CLS; i += blockDim.x) sb[i] = b2[i];
    __syncthreads();

    int lane = threadIdx.x & 31;
    int wrp  = threadIdx.x >> 5;
    int node = blockIdx.x * 8 + wrp;
    if (node >= nNodes) return;

    float4 acc = warp_gather(node, lane, g_h);

    if (lane < 4)
        *reinterpret_cast<float4*>(&sv[wrp][lane * 4]) = acc;
    __syncwarp();

    // lane computes class `lane`; lanes 0-7 also class 32+lane
    int c1 = 32 + (lane & 7);
    float y0 = sb[lane];
    float y1 = sb[c1];
    #pragma unroll
    for (int k = 0; k < N_HID; k++) {
        float vk = sv[wrp][k];
        y0 = fmaf(vk, sW[k * N_CLS + lane], y0);
        y1 = fmaf(vk, sW[k * N_CLS + c1], y1);
    }
    bool has1 = (lane < 8);

    float m = has1 ? fmaxf(y0, y1) : y0;
    #pragma unroll
    for (int off = 16; off >= 1; off >>= 1)
        m = fmaxf(m, __shfl_xor_sync(0xffffffffu, m, off));

    float ssum = __expf(y0 - m) + (has1 ? __expf(y1 - m) : 0.f);
    #pragma unroll
    for (int off = 16; off >= 1; off >>= 1)
        ssum += __shfl_xor_sync(0xffffffffu, ssum, off);

    float lse = m + __logf(ssum);

    float* o = out + (size_t)node * N_CLS;
    o[lane] = y0 - lse;
    if (has1) o[c1] = y1 - lse;
}

// ---------------------------------------------------------------------------
// Launcher
// ---------------------------------------------------------------------------
extern "C" void kernel_launch(void* const* d_in, const int* in_sizes, int n_in,
                              void* d_out, int out_size)
{
    const float* x        = (const float*)d_in[0];
    const int*   edge_src = (const int*)  d_in[1];
    const int*   edge_dst = (const int*)  d_in[2];
    const float* edge_w   = (const float*)d_in[3];
    const float* W1       = (const float*)d_in[4];
    const float* b1       = (const float*)d_in[5];
    const float* W2       = (const float*)d_in[6];
    const float* b2       = (const float*)d_in[7];
    float* out = (float*)d_out;

    int nNodes = in_sizes[0] / N_FEAT;
    int nEdges = in_sizes[1];
    int nb = (nNodes + SCAN_B - 1) / SCAN_B;

    // CSR build (dst buckets)
    zero_deg_kernel<<<(nNodes + 255) / 256, 256>>>(nNodes);
    hist_kernel<<<(nEdges + 255) / 256, 256>>>(edge_dst, nEdges);
    scanA_kernel<<<nb, SCAN_B>>>(nNodes);
    scanB_kernel<<<1, MAX_NB>>>(nb);
    scanC_kernel<<<(nNodes + 255) / 256, 256>>>(nNodes);
    scatter_kernel<<<(nEdges + 255) / 256, 256>>>(edge_src, edge_dst, edge_w, nEdges);

    // dense projection
    gemm1_kernel<<<(nNodes + 255) / 256, 256>>>(x, W1, nNodes);

    // warp-per-node gathers (8 nodes per 256-thread block)
    int gblocks = (nNodes + 7) / 8;
    gconv1_kernel<<<gblocks, 256>>>(b1, nNodes);
    gconv2_head_kernel<<<gblocks, 256>>>(W2, b2, out, nNodes);
}